// round 2
// baseline (speedup 1.0000x reference)
#include <cuda_runtime.h>
#include <math.h>

// Problem constants
constexpr int cB = 8;
constexpr int cR = 64;
constexpr int cC = 16;
constexpr int cD = 128;
constexpr int cN = 2016;          // R*(R-1)/2
constexpr int cCD = cC * cD;      // 2048
constexpr int cP = 16;            // pairs per CTA
constexpr int cTILES = cN / cP;   // 126
constexpr int NTHREADS = 256;

// Scratch (allocation-free rule: __device__ globals)
__device__ float g_Yh[(size_t)cB * cR * cCD];            // batch @ hW            (4MB)
__device__ float g_Yg[(size_t)cB * cR * cCD];            // batch @ gW + gb       (4MB)
__device__ float g_Km[(size_t)cB * cR * cCD];            // batch @ kW + kb       (4MB)
__device__ float g_Xm[(size_t)cB * cN * cCD];            // x_mid scratch         (132MB)

// Shared memory layout (float offsets)
constexpr int OFF_WS  = 0;                 // 128*128 weight buffer (qW then s1W)
constexpr int OFF_XS  = OFF_WS + cD * cD;  // 16384 : P*CD tile buffer (x_mid -> q -> x_final)
constexpr int OFF_AL  = OFF_XS + cP * cCD; // 49152 : alpha P*R
constexpr int OFF_HB  = OFF_AL + cP * cR;  // 50176
constexpr int OFF_QB  = OFF_HB + cD;       // 50304
constexpr int OFF_S1B = OFF_QB + cD;       // 50432
constexpr int OFF_S2W = OFF_S1B + cD;      // 50560
constexpr int OFF_MSK = OFF_S2W + cD;      // 50688 (16)
constexpr int OFF_SC  = OFF_MSK + cC;      // 50704 (16)
constexpr int OFF_RI  = OFF_SC + cP;       // 50720 (16, int)
constexpr int OFF_CI  = OFF_RI + cP;       // 50736 (16, int)
constexpr int OFF_S2B = OFF_CI + cP;       // 50752 (1)
constexpr int SMEM_FLOATS = OFF_S2B + 8;   // pad
constexpr int SMEM_BYTES  = SMEM_FLOATS * 4;  // ~203 KB

__device__ __forceinline__ float sigmoidf_(float x) { return 1.0f / (1.0f + __expf(-x)); }

// ---------------------------------------------------------------------------
// Kernel 1: precompute Yh = batch@hW, Yg = batch@gW + gb, Km = batch@kW + kb
// grid = B*R CTAs, 128 threads (thread = output column d)
// ---------------------------------------------------------------------------
__global__ __launch_bounds__(128) void phylo_precompute(
    const float* __restrict__ batch,
    const float* __restrict__ hW,
    const float* __restrict__ gW, const float* __restrict__ gb,
    const float* __restrict__ kW, const float* __restrict__ kb)
{
    __shared__ float xs[cCD];  // 8KB: one (b,r) row-block C x D
    const int br  = blockIdx.x;                 // b*R + r
    const int tid = threadIdx.x;                // 0..127 = d
    const float* src = batch + (size_t)br * cCD;
    for (int i = tid; i < cCD; i += 128) xs[i] = src[i];
    __syncthreads();

    const int d = tid;
    float accH[cC], accG[cC], accK[cC];
    const float gbd = gb[d], kbd = kb[d];
#pragma unroll
    for (int c = 0; c < cC; c++) { accH[c] = 0.0f; accG[c] = gbd; accK[c] = kbd; }

    for (int kk = 0; kk < cD; kk++) {
        const float wh = hW[kk * cD + d];
        const float wg = gW[kk * cD + d];
        const float wk = kW[kk * cD + d];
#pragma unroll
        for (int c = 0; c < cC; c++) {
            const float x = xs[c * cD + kk];
            accH[c] = fmaf(x, wh, accH[c]);
            accG[c] = fmaf(x, wg, accG[c]);
            accK[c] = fmaf(x, wk, accK[c]);
        }
    }
    const size_t base = (size_t)br * cCD + d;
#pragma unroll
    for (int c = 0; c < cC; c++) {
        g_Yh[base + c * cD] = accH[c];
        g_Yg[base + c * cD] = accG[c];
        g_Km[base + c * cD] = accK[c];
    }
}

// ---------------------------------------------------------------------------
// Kernel 2: main fused kernel. grid = (TILES, B), 256 threads, ~203KB dyn smem
// ---------------------------------------------------------------------------
__global__ __launch_bounds__(NTHREADS, 1) void phylo_main(
    const float* __restrict__ batch,
    const float* __restrict__ seq_mask,
    const int*   __restrict__ rowi,
    const int*   __restrict__ coli,
    const float* __restrict__ hb,
    const float* __restrict__ qW, const float* __restrict__ qb,
    const float* __restrict__ s1W, const float* __restrict__ s1b,
    const float* __restrict__ s2W, const float* __restrict__ s2b,
    float* __restrict__ out)
{
    extern __shared__ float sm[];
    float* Ws   = sm + OFF_WS;
    float* Xs   = sm + OFF_XS;
    float* Al   = sm + OFF_AL;
    float* hb_s = sm + OFF_HB;
    float* qb_s = sm + OFF_QB;
    float* s1b_s= sm + OFF_S1B;
    float* s2w_s= sm + OFF_S2W;
    float* msk_s= sm + OFF_MSK;
    float* sc_s = sm + OFF_SC;
    int*   ri_s = (int*)(sm + OFF_RI);
    int*   ci_s = (int*)(sm + OFF_CI);

    const int tile = blockIdx.x;
    const int b    = blockIdx.y;
    const int tid  = threadIdx.x;
    const int wid  = tid >> 5;
    const int lane = tid & 31;

    // ---- init small smem + load qW ----
    if (tid < cD) {
        hb_s[tid]  = hb[tid];
        qb_s[tid]  = qb[tid];
        s1b_s[tid] = s1b[tid];
        s2w_s[tid] = s2W[tid];
    }
    if (tid < cC) msk_s[tid] = seq_mask[b * cC + tid];
    if (tid < cP) {
        const int n = tile * cP + tid;
        ri_s[tid] = rowi[n];
        ci_s[tid] = coli[n];
        sc_s[tid] = 0.0f;
    }
    if (tid == 0) sm[OFF_S2B] = s2b[0];
    for (int i = tid * 4; i < cD * cD; i += NTHREADS * 4)
        *(float4*)&Ws[i] = *(const float4*)&qW[i];
    __syncthreads();

    // ---- Stage 1: x_mid = z*x_i + (1-z)*x_j, z = sigmoid(Yh_i - Yh_j + hb) ----
    for (int p = 0; p < cP; p++) {
        const int ri = ri_s[p], ci = ci_s[p];
        const float* Yi = g_Yh + (size_t)(b * cR + ri) * cCD;
        const float* Yj = g_Yh + (size_t)(b * cR + ci) * cCD;
        const float* Xi = batch + (size_t)(b * cR + ri) * cCD;
        const float* Xj = batch + (size_t)(b * cR + ci) * cCD;
        float* Xg = g_Xm + (size_t)(b * cN + tile * cP + p) * cCD;
#pragma unroll
        for (int v = 0; v < 2; v++) {
            const int cd = tid * 8 + v * 4;
            const int d  = cd & (cD - 1);
            float4 yi = *(const float4*)&Yi[cd];
            float4 yj = *(const float4*)&Yj[cd];
            float4 xi = *(const float4*)&Xi[cd];
            float4 xj = *(const float4*)&Xj[cd];
            float4 o;
            { float z = sigmoidf_(yi.x - yj.x + hb_s[d + 0]); o.x = z * xi.x + (1.0f - z) * xj.x; }
            { float z = sigmoidf_(yi.y - yj.y + hb_s[d + 1]); o.y = z * xi.y + (1.0f - z) * xj.y; }
            { float z = sigmoidf_(yi.z - yj.z + hb_s[d + 2]); o.z = z * xi.z + (1.0f - z) * xj.z; }
            { float z = sigmoidf_(yi.w - yj.w + hb_s[d + 3]); o.w = z * xi.w + (1.0f - z) * xj.w; }
            *(float4*)&Xs[p * cCD + cd] = o;
            *(float4*)&Xg[cd] = o;
        }
    }
    __syncthreads();

    // ---- Stage 2: q = x_mid @ qW + qb, in-place over Xs (row-wise, 4 rows/warp) ----
    for (int rbase = wid * 32; rbase < (wid + 1) * 32; rbase += 4) {
        float acc[4][4];
#pragma unroll
        for (int rr = 0; rr < 4; rr++)
#pragma unroll
            for (int u = 0; u < 4; u++) acc[rr][u] = qb_s[lane * 4 + u];
        for (int kk = 0; kk < cD; kk++) {
            float4 wv = *(float4*)&Ws[kk * cD + lane * 4];
#pragma unroll
            for (int rr = 0; rr < 4; rr++) {
                const float xv = Xs[(rbase + rr) * cD + kk];  // smem broadcast
                acc[rr][0] = fmaf(xv, wv.x, acc[rr][0]);
                acc[rr][1] = fmaf(xv, wv.y, acc[rr][1]);
                acc[rr][2] = fmaf(xv, wv.z, acc[rr][2]);
                acc[rr][3] = fmaf(xv, wv.w, acc[rr][3]);
            }
        }
        __syncwarp();
#pragma unroll
        for (int rr = 0; rr < 4; rr++)
            *(float4*)&Xs[(rbase + rr) * cD + lane * 4] =
                make_float4(acc[rr][0], acc[rr][1], acc[rr][2], acc[rr][3]);
        __syncwarp();
    }
    __syncthreads();

    // ---- Stage 3: alpha[p][r] = <q[p], K[b,r]> (warp = 8 r, quad per r) ----
    {
        const int rl = lane >> 2;       // 0..7
        const int s  = lane & 3;        // 0..3
        const int r  = wid * 8 + rl;
        const float* Kr = g_Km + (size_t)(b * cR + r) * cCD;
        float acc[cP];
#pragma unroll
        for (int p = 0; p < cP; p++) acc[p] = 0.0f;
        for (int i = s * 4; i < cCD; i += 16) {
            float4 kv = *(const float4*)&Kr[i];
#pragma unroll
            for (int p = 0; p < cP; p++) {
                float4 qv = *(float4*)&Xs[p * cCD + i];
                acc[p] = fmaf(kv.x, qv.x, acc[p]);
                acc[p] = fmaf(kv.y, qv.y, acc[p]);
                acc[p] = fmaf(kv.z, qv.z, acc[p]);
                acc[p] = fmaf(kv.w, qv.w, acc[p]);
            }
        }
#pragma unroll
        for (int p = 0; p < cP; p++) {
            acc[p] += __shfl_xor_sync(0xffffffffu, acc[p], 1);
            acc[p] += __shfl_xor_sync(0xffffffffu, acc[p], 2);
        }
        if (s == 0)
#pragma unroll
            for (int p = 0; p < cP; p++) Al[p * cR + r] = acc[p];
    }
    __syncthreads();

    // ---- Stage 4: masked softmax over r (warp handles 2 p) ----
    {
        const float scale = rsqrtf((float)(cD * cC));
#pragma unroll
        for (int pp = 0; pp < 2; pp++) {
            const int p = wid * 2 + pp;
            const int ri = ri_s[p], ci = ci_s[p];
            float v0 = Al[p * cR + lane];
            float v1 = Al[p * cR + lane + 32];
            v0 = (lane == ri || lane == ci) ? -INFINITY : v0 * scale;
            const int l2 = lane + 32;
            v1 = (l2 == ri || l2 == ci) ? -INFINITY : v1 * scale;
            float mx = fmaxf(v0, v1);
#pragma unroll
            for (int o = 16; o; o >>= 1) mx = fmaxf(mx, __shfl_xor_sync(0xffffffffu, mx, o));
            float e0 = expf(v0 - mx);
            float e1 = expf(v1 - mx);
            float sum = e0 + e1;
#pragma unroll
            for (int o = 16; o; o >>= 1) sum += __shfl_xor_sync(0xffffffffu, sum, o);
            const float inv = 1.0f / sum;
            Al[p * cR + lane]      = e0 * inv;
            Al[p * cR + lane + 32] = e1 * inv;
        }
    }
    __syncthreads();

    // ---- Stage 5+6: x_glob & g accumulation, blend, write x_final into Xs ----
    {
        const float* Bb = batch + (size_t)b * cR * cCD;
        const float* Gg = g_Yg + (size_t)b * cR * cCD;
        for (int ph = 0; ph < 2; ph++) {
            for (int ch = 0; ch < 2; ch++) {
                const int cd = ch * 1024 + tid * 4;
                float4 ax[8], ag[8];
#pragma unroll
                for (int pp = 0; pp < 8; pp++) {
                    ax[pp] = make_float4(0.f, 0.f, 0.f, 0.f);
                    ag[pp] = make_float4(0.f, 0.f, 0.f, 0.f);
                }
                for (int r = 0; r < cR; r++) {
                    float4 bv = *(const float4*)&Bb[(size_t)r * cCD + cd];
                    float4 gv = *(const float4*)&Gg[(size_t)r * cCD + cd];
#pragma unroll
                    for (int pp = 0; pp < 8; pp++) {
                        const float a = Al[(ph * 8 + pp) * cR + r];  // smem broadcast
                        ax[pp].x = fmaf(a, bv.x, ax[pp].x);
                        ax[pp].y = fmaf(a, bv.y, ax[pp].y);
                        ax[pp].z = fmaf(a, bv.z, ax[pp].z);
                        ax[pp].w = fmaf(a, bv.w, ax[pp].w);
                        ag[pp].x = fmaf(a, gv.x, ag[pp].x);
                        ag[pp].y = fmaf(a, gv.y, ag[pp].y);
                        ag[pp].z = fmaf(a, gv.z, ag[pp].z);
                        ag[pp].w = fmaf(a, gv.w, ag[pp].w);
                    }
                }
#pragma unroll
                for (int pp = 0; pp < 8; pp++) {
                    const int p = ph * 8 + pp;
                    const float* xm = g_Xm + (size_t)(b * cN + tile * cP + p) * cCD + cd;
                    float4 xmv = *(const float4*)xm;
                    float4 xf;
                    { float w = sigmoidf_(ag[pp].x); xf.x = (1.f - w) * xmv.x + w * ax[pp].x; }
                    { float w = sigmoidf_(ag[pp].y); xf.y = (1.f - w) * xmv.y + w * ax[pp].y; }
                    { float w = sigmoidf_(ag[pp].z); xf.z = (1.f - w) * xmv.z + w * ax[pp].z; }
                    { float w = sigmoidf_(ag[pp].w); xf.w = (1.f - w) * xmv.w + w * ax[pp].w; }
                    *(float4*)&Xs[p * cCD + cd] = xf;
                }
            }
        }
    }
    __syncthreads();

    // ---- load s1W over qW ----
    for (int i = tid * 4; i < cD * cD; i += NTHREADS * 4)
        *(float4*)&Ws[i] = *(const float4*)&s1W[i];
    __syncthreads();

    // ---- Stage 7: s = gelu(x@s1W+s1b)@s2W + s2b ; scores[p] += s*mask[c] ----
    {
        const float s2bv = sm[OFF_S2B];
        for (int rbase = wid * 32; rbase < (wid + 1) * 32; rbase += 4) {
            float acc[4][4];
#pragma unroll
            for (int rr = 0; rr < 4; rr++)
#pragma unroll
                for (int u = 0; u < 4; u++) acc[rr][u] = s1b_s[lane * 4 + u];
            for (int kk = 0; kk < cD; kk++) {
                float4 wv = *(float4*)&Ws[kk * cD + lane * 4];
#pragma unroll
                for (int rr = 0; rr < 4; rr++) {
                    const float xv = Xs[(rbase + rr) * cD + kk];
                    acc[rr][0] = fmaf(xv, wv.x, acc[rr][0]);
                    acc[rr][1] = fmaf(xv, wv.y, acc[rr][1]);
                    acc[rr][2] = fmaf(xv, wv.z, acc[rr][2]);
                    acc[rr][3] = fmaf(xv, wv.w, acc[rr][3]);
                }
            }
#pragma unroll
            for (int rr = 0; rr < 4; rr++) {
                float part = 0.0f;
#pragma unroll
                for (int u = 0; u < 4; u++) {
                    const float t  = acc[rr][u];
                    const float ge = 0.5f * t * (1.0f + erff(t * 0.70710678118654752f));
                    part = fmaf(ge, s2w_s[lane * 4 + u], part);
                }
#pragma unroll
                for (int o = 16; o; o >>= 1) part += __shfl_xor_sync(0xffffffffu, part, o);
                if (lane == 0) {
                    const int row = rbase + rr;
                    const int p = row >> 4, c = row & 15;
                    atomicAdd(&sc_s[p], (part + s2bv) * msk_s[c]);
                }
            }
        }
    }
    __syncthreads();

    if (tid < cP) out[(size_t)b * cN + tile * cP + tid] = sc_s[tid];
}

// ---------------------------------------------------------------------------
extern "C" void kernel_launch(void* const* d_in, const int* in_sizes, int n_in,
                              void* d_out, int out_size)
{
    const float* batch    = (const float*)d_in[0];
    const float* seq_mask = (const float*)d_in[1];
    const int*   rowi     = (const int*)d_in[2];
    const int*   coli     = (const int*)d_in[3];
    const float* hW       = (const float*)d_in[4];
    const float* hb       = (const float*)d_in[5];
    const float* gW       = (const float*)d_in[6];
    const float* gb       = (const float*)d_in[7];
    const float* qW       = (const float*)d_in[8];
    const float* qb       = (const float*)d_in[9];
    const float* kW       = (const float*)d_in[10];
    const float* kb       = (const float*)d_in[11];
    const float* s1W      = (const float*)d_in[12];
    const float* s1b      = (const float*)d_in[13];
    const float* s2W      = (const float*)d_in[14];
    const float* s2b      = (const float*)d_in[15];
    float* out = (float*)d_out;

    cudaFuncSetAttribute(phylo_main, cudaFuncAttributeMaxDynamicSharedMemorySize, SMEM_BYTES);

    phylo_precompute<<<cB * cR, 128>>>(batch, hW, gW, gb, kW, kb);
    phylo_main<<<dim3(cTILES, cB), NTHREADS, SMEM_BYTES>>>(
        batch, seq_mask, rowi, coli, hb, qW, qb, s1W, s1b, s2W, s2b, out);
}

// round 3
// speedup vs baseline: 1.1921x; 1.1921x over previous
#include <cuda_runtime.h>
#include <math.h>

// Problem constants
constexpr int cB = 8;
constexpr int cR = 64;
constexpr int cC = 16;
constexpr int cD = 128;
constexpr int cN = 2016;          // R*(R-1)/2
constexpr int cCD = cC * cD;      // 2048
constexpr int cP = 16;            // pairs per CTA
constexpr int cTILES = cN / cP;   // 126
constexpr int NT = 512;           // 16 warps

// Scratch (allocation-free rule: __device__ globals)
__device__ float g_Yh[(size_t)cB * cR * cCD];   // batch @ hW          (4MB)
__device__ float g_Yg[(size_t)cB * cR * cCD];   // batch @ gW + gb     (4MB)
__device__ float g_Km[(size_t)cB * cR * cCD];   // batch @ kW + kb     (4MB)

// Shared memory layout (float offsets)
constexpr int OFF_WS  = 0;                 // 128*128 weight buffer (qW then s1W)
constexpr int OFF_XS  = OFF_WS + cD * cD;  // 16384 : P*CD tile (x_mid -> q -> x_final)
constexpr int OFF_AL  = OFF_XS + cP * cCD; // 49152 : alpha P*R
constexpr int OFF_HB  = OFF_AL + cP * cR;  // 50176
constexpr int OFF_QB  = OFF_HB + cD;
constexpr int OFF_S1B = OFF_QB + cD;
constexpr int OFF_S2W = OFF_S1B + cD;
constexpr int OFF_MSK = OFF_S2W + cD;
constexpr int OFF_SC  = OFF_MSK + cC;
constexpr int OFF_RI  = OFF_SC + cP;
constexpr int OFF_CI  = OFF_RI + cP;
constexpr int OFF_S2B = OFF_CI + cP;
constexpr int SMEM_FLOATS = OFF_S2B + 8;
constexpr int SMEM_BYTES  = SMEM_FLOATS * 4;   // ~203 KB

typedef unsigned long long u64;

__device__ __forceinline__ float sigmoidf_(float x) { return 1.0f / (1.0f + __expf(-x)); }

__device__ __forceinline__ u64 pk2(float lo, float hi) {
    u64 r; asm("mov.b64 %0,{%1,%2};" : "=l"(r) : "f"(lo), "f"(hi)); return r;
}
__device__ __forceinline__ float2 upk2(u64 v) {
    float2 f; asm("mov.b64 {%0,%1},%2;" : "=f"(f.x), "=f"(f.y) : "l"(v)); return f;
}
__device__ __forceinline__ u64 ffma2(u64 a, u64 b, u64 c) {
    u64 d; asm("fma.rn.f32x2 %0,%1,%2,%3;" : "=l"(d) : "l"(a), "l"(b), "l"(c)); return d;
}

// ---------------------------------------------------------------------------
// Kernel 1: precompute Yh = batch@hW, Yg = batch@gW + gb, Km = batch@kW + kb
// ---------------------------------------------------------------------------
__global__ __launch_bounds__(128) void phylo_precompute(
    const float* __restrict__ batch,
    const float* __restrict__ hW,
    const float* __restrict__ gW, const float* __restrict__ gb,
    const float* __restrict__ kW, const float* __restrict__ kb)
{
    __shared__ float xs[cCD];
    const int br  = blockIdx.x;
    const int tid = threadIdx.x;
    const float* src = batch + (size_t)br * cCD;
    for (int i = tid; i < cCD; i += 128) xs[i] = src[i];
    __syncthreads();

    const int d = tid;
    float accH[cC], accG[cC], accK[cC];
    const float gbd = gb[d], kbd = kb[d];
#pragma unroll
    for (int c = 0; c < cC; c++) { accH[c] = 0.0f; accG[c] = gbd; accK[c] = kbd; }

    for (int kk = 0; kk < cD; kk++) {
        const float wh = hW[kk * cD + d];
        const float wg = gW[kk * cD + d];
        const float wk = kW[kk * cD + d];
#pragma unroll
        for (int c = 0; c < cC; c++) {
            const float x = xs[c * cD + kk];
            accH[c] = fmaf(x, wh, accH[c]);
            accG[c] = fmaf(x, wg, accG[c]);
            accK[c] = fmaf(x, wk, accK[c]);
        }
    }
    const size_t base = (size_t)br * cCD + d;
#pragma unroll
    for (int c = 0; c < cC; c++) {
        g_Yh[base + c * cD] = accH[c];
        g_Yg[base + c * cD] = accG[c];
        g_Km[base + c * cD] = accK[c];
    }
}

// ---------------------------------------------------------------------------
// Kernel 2: main fused kernel. grid = (TILES, B), 512 threads, ~203KB dyn smem
// ---------------------------------------------------------------------------
__global__ __launch_bounds__(NT, 1) void phylo_main(
    const float* __restrict__ batch,
    const float* __restrict__ seq_mask,
    const int*   __restrict__ rowi,
    const int*   __restrict__ coli,
    const float* __restrict__ hb,
    const float* __restrict__ qW, const float* __restrict__ qb,
    const float* __restrict__ s1W, const float* __restrict__ s1b,
    const float* __restrict__ s2W, const float* __restrict__ s2b,
    float* __restrict__ out)
{
    extern __shared__ float sm[];
    float* Ws    = sm + OFF_WS;
    float* Xs    = sm + OFF_XS;
    float* Al    = sm + OFF_AL;
    float* hb_s  = sm + OFF_HB;
    float* qb_s  = sm + OFF_QB;
    float* s1b_s = sm + OFF_S1B;
    float* s2w_s = sm + OFF_S2W;
    float* msk_s = sm + OFF_MSK;
    float* sc_s  = sm + OFF_SC;
    int*   ri_s  = (int*)(sm + OFF_RI);
    int*   ci_s  = (int*)(sm + OFF_CI);

    const int tile = blockIdx.x;
    const int b    = blockIdx.y;
    const int tid  = threadIdx.x;
    const int wid  = tid >> 5;
    const int lane = tid & 31;
    const int cd   = tid * 4;        // 512*4 = 2048 = full CD
    const int d0   = cd & (cD - 1);

    // ---- init small smem + load qW ----
    if (tid < cD) {
        hb_s[tid]  = hb[tid];
        qb_s[tid]  = qb[tid];
        s1b_s[tid] = s1b[tid];
        s2w_s[tid] = s2W[tid];
    }
    if (tid < cC) msk_s[tid] = seq_mask[b * cC + tid];
    if (tid < cP) {
        const int n = tile * cP + tid;
        ri_s[tid] = rowi[n];
        ci_s[tid] = coli[n];
        sc_s[tid] = 0.0f;
    }
    if (tid == 0) sm[OFF_S2B] = s2b[0];
    for (int i = tid * 4; i < cD * cD; i += NT * 4)
        *(float4*)&Ws[i] = *(const float4*)&qW[i];
    __syncthreads();

    // ---- Stage 1: x_mid = z*x_i + (1-z)*x_j into Xs ----
    for (int p = 0; p < cP; p++) {
        const int ri = ri_s[p], ci = ci_s[p];
        const float* Yi = g_Yh + (b * cR + ri) * cCD;
        const float* Yj = g_Yh + (b * cR + ci) * cCD;
        const float* Xi = batch + (b * cR + ri) * cCD;
        const float* Xj = batch + (b * cR + ci) * cCD;
        float4 yi = *(const float4*)&Yi[cd];
        float4 yj = *(const float4*)&Yj[cd];
        float4 xi = *(const float4*)&Xi[cd];
        float4 xj = *(const float4*)&Xj[cd];
        float4 o;
        { float z = sigmoidf_(yi.x - yj.x + hb_s[d0 + 0]); o.x = z * xi.x + (1.0f - z) * xj.x; }
        { float z = sigmoidf_(yi.y - yj.y + hb_s[d0 + 1]); o.y = z * xi.y + (1.0f - z) * xj.y; }
        { float z = sigmoidf_(yi.z - yj.z + hb_s[d0 + 2]); o.z = z * xi.z + (1.0f - z) * xj.z; }
        { float z = sigmoidf_(yi.w - yj.w + hb_s[d0 + 3]); o.w = z * xi.w + (1.0f - z) * xj.w; }
        *(float4*)&Xs[p * cCD + cd] = o;
    }
    __syncthreads();

    // ---- Stage 2: q = x_mid @ qW + qb, in-place over Xs ----
    // Warp wid owns rows [wid*16, wid*16+16), processed 8 at a time.
    // Packed along K: acc holds (even-k partial, odd-k partial).
    for (int g = 0; g < 2; g++) {
        const int rbase = wid * 16 + g * 8;
        u64 acc[8][4];
#pragma unroll
        for (int rr = 0; rr < 8; rr++)
#pragma unroll
            for (int u = 0; u < 4; u++) acc[rr][u] = 0ull;
        for (int kp = 0; kp < 64; kp++) {
            float4 w0 = *(float4*)&Ws[(2 * kp) * cD + lane * 4];
            float4 w1 = *(float4*)&Ws[(2 * kp + 1) * cD + lane * 4];
            u64 wp0 = pk2(w0.x, w1.x), wp1 = pk2(w0.y, w1.y);
            u64 wp2 = pk2(w0.z, w1.z), wp3 = pk2(w0.w, w1.w);
#pragma unroll
            for (int rr = 0; rr < 8; rr++) {
                u64 xp = *(u64*)&Xs[(rbase + rr) * cD + 2 * kp];   // LDS.64 broadcast
                acc[rr][0] = ffma2(xp, wp0, acc[rr][0]);
                acc[rr][1] = ffma2(xp, wp1, acc[rr][1]);
                acc[rr][2] = ffma2(xp, wp2, acc[rr][2]);
                acc[rr][3] = ffma2(xp, wp3, acc[rr][3]);
            }
        }
        __syncwarp();
#pragma unroll
        for (int rr = 0; rr < 8; rr++) {
            float4 o;
            float2 a0 = upk2(acc[rr][0]); o.x = a0.x + a0.y + qb_s[lane * 4 + 0];
            float2 a1 = upk2(acc[rr][1]); o.y = a1.x + a1.y + qb_s[lane * 4 + 1];
            float2 a2 = upk2(acc[rr][2]); o.z = a2.x + a2.y + qb_s[lane * 4 + 2];
            float2 a3 = upk2(acc[rr][3]); o.w = a3.x + a3.y + qb_s[lane * 4 + 3];
            *(float4*)&Xs[(rbase + rr) * cD + lane * 4] = o;
        }
        __syncwarp();
    }
    __syncthreads();

    // ---- Stage 3: alpha[p][r] = <q[p], K[b,r]>, packed along K ----
    {
        const int r = wid * 4 + (lane >> 3);   // 64 r over 16 warps
        const int s = lane & 7;                // 8 lanes per r
        const float* Kr = g_Km + (b * cR + r) * cCD;
        u64 acc[cP];
#pragma unroll
        for (int p = 0; p < cP; p++) acc[p] = 0ull;
#pragma unroll 2
        for (int i = s * 4; i < cCD; i += 32) {
            ulonglong2 kv = *(const ulonglong2*)&Kr[i];
#pragma unroll
            for (int p = 0; p < cP; p++) {
                ulonglong2 qv = *(ulonglong2*)&Xs[p * cCD + i];
                acc[p] = ffma2(kv.x, qv.x, acc[p]);
                acc[p] = ffma2(kv.y, qv.y, acc[p]);
            }
        }
#pragma unroll
        for (int p = 0; p < cP; p++) {
            float2 t = upk2(acc[p]);
            float v = t.x + t.y;
            v += __shfl_xor_sync(0xffffffffu, v, 1);
            v += __shfl_xor_sync(0xffffffffu, v, 2);
            v += __shfl_xor_sync(0xffffffffu, v, 4);
            if (s == 0) Al[p * cR + r] = v;
        }
    }
    __syncthreads();

    // ---- Stage 4: masked softmax over r (warp wid = pair wid) ----
    {
        const float scale = rsqrtf((float)(cD * cC));
        const int p = wid;
        const int ri = ri_s[p], ci = ci_s[p];
        float v0 = Al[p * cR + lane];
        float v1 = Al[p * cR + lane + 32];
        v0 = (lane == ri || lane == ci) ? -INFINITY : v0 * scale;
        const int l2 = lane + 32;
        v1 = (l2 == ri || l2 == ci) ? -INFINITY : v1 * scale;
        float mx = fmaxf(v0, v1);
#pragma unroll
        for (int o = 16; o; o >>= 1) mx = fmaxf(mx, __shfl_xor_sync(0xffffffffu, mx, o));
        float e0 = __expf(v0 - mx);
        float e1 = __expf(v1 - mx);
        float sum = e0 + e1;
#pragma unroll
        for (int o = 16; o; o >>= 1) sum += __shfl_xor_sync(0xffffffffu, sum, o);
        const float inv = 1.0f / sum;
        Al[p * cR + lane]      = e0 * inv;
        Al[p * cR + lane + 32] = e1 * inv;
    }
    __syncthreads();

    // ---- Stage 5+6: x_glob & g accumulation, recompute x_mid, blend -> Xs ----
    {
        const float* Bb = batch + b * cR * cCD;
        const float* Gg = g_Yg + b * cR * cCD;
        for (int ph = 0; ph < 2; ph++) {
            u64 ax0[8], ax1[8], ag0[8], ag1[8];
#pragma unroll
            for (int pp = 0; pp < 8; pp++) { ax0[pp] = ax1[pp] = ag0[pp] = ag1[pp] = 0ull; }
            for (int r = 0; r < cR; r++) {
                ulonglong2 bv = *(const ulonglong2*)&Bb[r * cCD + cd];
                ulonglong2 gv = *(const ulonglong2*)&Gg[r * cCD + cd];
#pragma unroll
                for (int pp = 0; pp < 8; pp++) {
                    const float a = Al[(ph * 8 + pp) * cR + r];   // smem broadcast
                    const u64 a2 = pk2(a, a);
                    ax0[pp] = ffma2(a2, bv.x, ax0[pp]);
                    ax1[pp] = ffma2(a2, bv.y, ax1[pp]);
                    ag0[pp] = ffma2(a2, gv.x, ag0[pp]);
                    ag1[pp] = ffma2(a2, gv.y, ag1[pp]);
                }
            }
#pragma unroll
            for (int pp = 0; pp < 8; pp++) {
                const int p = ph * 8 + pp;
                const int ri = ri_s[p], ci = ci_s[p];
                float4 yi = *(const float4*)&g_Yh[(b * cR + ri) * cCD + cd];
                float4 yj = *(const float4*)&g_Yh[(b * cR + ci) * cCD + cd];
                float4 xi = *(const float4*)&batch[(b * cR + ri) * cCD + cd];
                float4 xj = *(const float4*)&batch[(b * cR + ci) * cCD + cd];
                float2 x0 = upk2(ax0[pp]), x1 = upk2(ax1[pp]);
                float2 g0 = upk2(ag0[pp]), g1 = upk2(ag1[pp]);
                float4 xf;
                {
                    float z = sigmoidf_(yi.x - yj.x + hb_s[d0 + 0]);
                    float xm = z * xi.x + (1.0f - z) * xj.x;
                    float w = sigmoidf_(g0.x);
                    xf.x = (1.0f - w) * xm + w * x0.x;
                }
                {
                    float z = sigmoidf_(yi.y - yj.y + hb_s[d0 + 1]);
                    float xm = z * xi.y + (1.0f - z) * xj.y;
                    float w = sigmoidf_(g0.y);
                    xf.y = (1.0f - w) * xm + w * x0.y;
                }
                {
                    float z = sigmoidf_(yi.z - yj.z + hb_s[d0 + 2]);
                    float xm = z * xi.z + (1.0f - z) * xj.z;
                    float w = sigmoidf_(g1.x);
                    xf.z = (1.0f - w) * xm + w * x1.x;
                }
                {
                    float z = sigmoidf_(yi.w - yj.w + hb_s[d0 + 3]);
                    float xm = z * xi.w + (1.0f - z) * xj.w;
                    float w = sigmoidf_(g1.y);
                    xf.w = (1.0f - w) * xm + w * x1.y;
                }
                *(float4*)&Xs[p * cCD + cd] = xf;
            }
        }
    }
    __syncthreads();

    // ---- load s1W over qW ----
    for (int i = tid * 4; i < cD * cD; i += NT * 4)
        *(float4*)&Ws[i] = *(const float4*)&s1W[i];
    __syncthreads();

    // ---- Stage 7: s = gelu(x@s1W+s1b)@s2W + s2b ; scores[p] += s*mask[c] ----
    {
        const float s2bv = sm[OFF_S2B];
        for (int g = 0; g < 2; g++) {
            const int rbase = wid * 16 + g * 8;
            u64 acc[8][4];
#pragma unroll
            for (int rr = 0; rr < 8; rr++)
#pragma unroll
                for (int u = 0; u < 4; u++) acc[rr][u] = 0ull;
            for (int kp = 0; kp < 64; kp++) {
                float4 w0 = *(float4*)&Ws[(2 * kp) * cD + lane * 4];
                float4 w1 = *(float4*)&Ws[(2 * kp + 1) * cD + lane * 4];
                u64 wp0 = pk2(w0.x, w1.x), wp1 = pk2(w0.y, w1.y);
                u64 wp2 = pk2(w0.z, w1.z), wp3 = pk2(w0.w, w1.w);
#pragma unroll
                for (int rr = 0; rr < 8; rr++) {
                    u64 xp = *(u64*)&Xs[(rbase + rr) * cD + 2 * kp];
                    acc[rr][0] = ffma2(xp, wp0, acc[rr][0]);
                    acc[rr][1] = ffma2(xp, wp1, acc[rr][1]);
                    acc[rr][2] = ffma2(xp, wp2, acc[rr][2]);
                    acc[rr][3] = ffma2(xp, wp3, acc[rr][3]);
                }
            }
#pragma unroll
            for (int rr = 0; rr < 8; rr++) {
                float part = 0.0f;
#pragma unroll
                for (int u = 0; u < 4; u++) {
                    float2 a = upk2(acc[rr][u]);
                    const float t = a.x + a.y + s1b_s[lane * 4 + u];
                    const float ge = 0.5f * t * (1.0f + erff(t * 0.70710678118654752f));
                    part = fmaf(ge, s2w_s[lane * 4 + u], part);
                }
#pragma unroll
                for (int o = 16; o; o >>= 1) part += __shfl_xor_sync(0xffffffffu, part, o);
                if (lane == 0) {
                    const int row = rbase + rr;
                    const int p = row >> 4, c = row & 15;
                    atomicAdd(&sc_s[p], (part + s2bv) * msk_s[c]);
                }
            }
        }
    }
    __syncthreads();

    if (tid < cP) out[b * cN + tile * cP + tid] = sc_s[tid];
}

// ---------------------------------------------------------------------------
extern "C" void kernel_launch(void* const* d_in, const int* in_sizes, int n_in,
                              void* d_out, int out_size)
{
    const float* batch    = (const float*)d_in[0];
    const float* seq_mask = (const float*)d_in[1];
    const int*   rowi     = (const int*)d_in[2];
    const int*   coli     = (const int*)d_in[3];
    const float* hW       = (const float*)d_in[4];
    const float* hb       = (const float*)d_in[5];
    const float* gW       = (const float*)d_in[6];
    const float* gb       = (const float*)d_in[7];
    const float* qW       = (const float*)d_in[8];
    const float* qb       = (const float*)d_in[9];
    const float* kW       = (const float*)d_in[10];
    const float* kb       = (const float*)d_in[11];
    const float* s1W      = (const float*)d_in[12];
    const float* s1b      = (const float*)d_in[13];
    const float* s2W      = (const float*)d_in[14];
    const float* s2b      = (const float*)d_in[15];
    float* out = (float*)d_out;

    cudaFuncSetAttribute(phylo_main, cudaFuncAttributeMaxDynamicSharedMemorySize, SMEM_BYTES);

    phylo_precompute<<<cB * cR, 128>>>(batch, hW, gW, gb, kW, kb);
    phylo_main<<<dim3(cTILES, cB), NT, SMEM_BYTES>>>(
        batch, seq_mask, rowi, coli, hb, qW, qb, s1W, s1b, s2W, s2b, out);
}